// round 16
// baseline (speedup 1.0000x reference)
#include <cuda_runtime.h>
#include <cstdint>

#define B_ 2
#define S_ 2048
#define D_ 1024
#define H_ 16
#define DEPTH_ 64
#define SCALE_ 0.125f
#define NEG_ (-1.0e9f)

// Scratch (device globals — no allocations allowed)
__device__ float g_Qh[B_*H_*S_*DEPTH_];
__device__ float g_Kh[B_*H_*S_*DEPTH_];
__device__ float g_Vh[B_*H_*S_*DEPTH_];
__device__ float g_ctx[B_*S_*D_];
__device__ float g_rinv[B_*H_*S_];

__device__ __forceinline__ unsigned f2tf32(float f) {
    unsigned u; asm("cvt.rna.tf32.f32 %0, %1;" : "=r"(u) : "f"(f)); return u;
}

#define MMA_TF32(d, a, b)                                                     \
    asm volatile(                                                             \
        "mma.sync.aligned.m16n8k8.row.col.f32.tf32.tf32.f32 "                 \
        "{%0,%1,%2,%3},{%4,%5,%6,%7},{%8,%9},{%0,%1,%2,%3};"                  \
        : "+f"(d[0]), "+f"(d[1]), "+f"(d[2]), "+f"(d[3])                      \
        : "r"(a[0]), "r"(a[1]), "r"(a[2]), "r"(a[3]), "r"(b[0]), "r"(b[1]))

__device__ __forceinline__ uint32_t smem_u32(const void* p) {
    uint32_t a;
    asm("{ .reg .u64 t; cvta.to.shared.u64 t, %1; cvt.u32.u64 %0, t; }"
        : "=r"(a) : "l"(p));
    return a;
}

#define CP_ASYNC16(dst, src) \
    asm volatile("cp.async.cg.shared.global [%0], [%1], 16;" :: "r"(dst), "l"(src) : "memory")
#define CP_COMMIT() asm volatile("cp.async.commit_group;" ::: "memory")
#define CP_WAIT1()  asm volatile("cp.async.wait_group 1;" ::: "memory")
#define CP_WAIT0()  asm volatile("cp.async.wait_group 0;" ::: "memory")

// ---------------------------------------------------------------------------
// QKV tf32 GEMM: 256x128 CTA tile (512 threads), BK=32, 2-stage cp.async.
// Halved barrier count vs BK=16: 64 MMAs per barrier-phase per warp.
// A stride 36 (conflict-free: bank = (4*gid + tid4) mod 32), B stride 132.
// ---------------------------------------------------------------------------
#define GASF(st, r, c) AsG[(st) * 9216 + (r) * 36 + (c)]
#define GBSF(st, r, c) BsG[(st) * 4224 + (r) * 132 + (c)]
#define QKV_SMEM_BYTES ((2 * 9216 + 2 * 4224) * 4)

__global__ __launch_bounds__(512, 1)
void gemm_qkv_kernel(const float* __restrict__ A0, const float* __restrict__ W0,
                     const float* __restrict__ bias0, float* __restrict__ C0,
                     const float* A1, const float* W1, const float* bias1, float* C1,
                     const float* A2, const float* W2, const float* bias2, float* C2)
{
    extern __shared__ float gsm[];
    float* AsG = gsm;                 // [2][256][36]
    float* BsG = gsm + 2 * 9216;      // [2][32][132]

    const float* A = A0; const float* W = W0; const float* bias = bias0; float* C = C0;
    if (blockIdx.z == 1) { A = A1; W = W1; bias = bias1; C = C1; }
    else if (blockIdx.z == 2) { A = A2; W = W2; bias = bias2; C = C2; }

    const int t    = threadIdx.x;
    const int m0   = blockIdx.y * 256;
    const int n0   = blockIdx.x * 128;
    const int lane = t & 31, warp = t >> 5;
    const int wm   = warp >> 2, wn = warp & 3;
    const int gid  = lane >> 2, tid4 = lane & 3;

    // staging maps (BK=32)
    const int ar = t >> 1,  ac = (t & 1) * 16;     // A: 256 rows x 32 cols, 4 f4/thr
    const int br = t >> 4,  bc = (t & 15) * 8;     // B: 32 rows x 128 cols, 2 f4/thr

    const float* Aptr = A + (size_t)(m0 + ar) * 1024 + ac;
    const float* Wptr = W + (size_t)br * 1024 + n0 + bc;

    uint32_t a_dst[2], b_dst[2];
#pragma unroll
    for (int s = 0; s < 2; s++) {
        a_dst[s] = smem_u32(&GASF(s, ar, ac));
        b_dst[s] = smem_u32(&GBSF(s, br, bc));
    }

    float acc[4][4][4];
#pragma unroll
    for (int i = 0; i < 4; i++)
#pragma unroll
        for (int j = 0; j < 4; j++)
#pragma unroll
            for (int c = 0; c < 4; c++) acc[i][j][c] = 0.f;

    // prologue: stage tiles 0 and 1 (each 32-K deep)
#pragma unroll
    for (int s = 0; s < 2; s++) {
        const int ko = s * 32;
        CP_ASYNC16(a_dst[s],      Aptr + ko);
        CP_ASYNC16(a_dst[s] + 16, Aptr + ko + 4);
        CP_ASYNC16(a_dst[s] + 32, Aptr + ko + 8);
        CP_ASYNC16(a_dst[s] + 48, Aptr + ko + 12);
        CP_ASYNC16(b_dst[s],      Wptr + (size_t)ko * 1024);
        CP_ASYNC16(b_dst[s] + 16, Wptr + (size_t)ko * 1024 + 4);
        CP_COMMIT();
    }

    for (int kt = 0; kt < 32; kt++) {
        const int cur = kt & 1;

        if (kt >= 31) CP_WAIT0(); else CP_WAIT1();
        __syncthreads();

#pragma unroll
        for (int s = 0; s < 4; s++) {
            unsigned af[4][4], bf[4][2];
#pragma unroll
            for (int i = 0; i < 4; i++) {
                const int r = wm * 64 + i * 16 + gid;
                const int kc = 8 * s + tid4;
                af[i][0] = f2tf32(GASF(cur, r, kc));
                af[i][1] = f2tf32(GASF(cur, r + 8, kc));
                af[i][2] = f2tf32(GASF(cur, r, kc + 4));
                af[i][3] = f2tf32(GASF(cur, r + 8, kc + 4));
            }
#pragma unroll
            for (int j = 0; j < 4; j++) {
                const int cn = wn * 32 + j * 8 + gid;
                bf[j][0] = f2tf32(GBSF(cur, 8 * s + tid4, cn));
                bf[j][1] = f2tf32(GBSF(cur, 8 * s + 4 + tid4, cn));
            }
#pragma unroll
            for (int i = 0; i < 4; i++)
#pragma unroll
                for (int j = 0; j < 4; j++) MMA_TF32(acc[i][j], af[i], bf[j]);
        }
        __syncthreads();

        if (kt + 2 < 32) {
            const int ko = (kt + 2) * 32;
            CP_ASYNC16(a_dst[cur],      Aptr + ko);
            CP_ASYNC16(a_dst[cur] + 16, Aptr + ko + 4);
            CP_ASYNC16(a_dst[cur] + 32, Aptr + ko + 8);
            CP_ASYNC16(a_dst[cur] + 48, Aptr + ko + 12);
            CP_ASYNC16(b_dst[cur],      Wptr + (size_t)ko * 1024);
            CP_ASYNC16(b_dst[cur] + 16, Wptr + (size_t)ko * 1024 + 4);
            CP_COMMIT();
        }
    }

#pragma unroll
    for (int i = 0; i < 4; i++) {
#pragma unroll
        for (int j = 0; j < 4; j++) {
            const int n = n0 + wn * 32 + j * 8 + tid4 * 2;
            const float b0 = bias[n], b1 = bias[n + 1];
#pragma unroll
            for (int half = 0; half < 2; half++) {
                const int m = m0 + wm * 64 + i * 16 + gid + half * 8;
                const float v0 = acc[i][j][half * 2 + 0] + b0;
                const float v1 = acc[i][j][half * 2 + 1] + b1;
                const int bb = m >> 11, s = m & 2047;
                const int h = n >> 6, dd = n & 63;
                float* dst = &C[(((size_t)(bb * H_ + h) << 11) + s) * DEPTH_ + dd];
                dst[0] = v0; dst[1] = v1;
            }
        }
    }
}

// ---------------------------------------------------------------------------
// FUSED tail kernel: out-projection GEMM (interleaved 256 blocks) + attn
// normalization (8192 streaming blocks, MLP-8, streaming hints). (round-15)
// ---------------------------------------------------------------------------
#define FAS(st, r, c) Asf[(st) * 2560 + (r) * 20 + (c)]
#define FBS(st, r, c) Bsf[(st) * 2112 + (r) * 132 + (c)]
#define FUSED_SMEM_BYTES ((2 * 2560 + 2 * 2112) * 4)
#define NORM_F4_PER_BLOCK 4096
#define FUSED_BLOCKS (512 + 8192 - 256)

__global__ __launch_bounds__(256, 2)
void fused_out_norm_kernel(const float* __restrict__ Actx,
                           const float* __restrict__ Wo,
                           const float* __restrict__ bo,
                           float* __restrict__ Cout,
                           float* __restrict__ attn)
{
    extern __shared__ float fsm[];
    const int bx = blockIdx.x;
    const int t  = threadIdx.x;

    const bool is_gemm = (bx < 512) && ((bx & 1) == 0);

    if (!is_gemm) {
        const int nidx = (bx < 512) ? (bx >> 1) : (256 + (bx - 512));
        float4* ap = (float4*)attn;
        const size_t base = (size_t)nidx * NORM_F4_PER_BLOCK + t;
#pragma unroll
        for (int g = 0; g < 2; g++) {
            float4 v[8]; float r[8]; size_t ii[8];
#pragma unroll
            for (int u = 0; u < 8; u++) {
                ii[u] = base + (g * 8 + u) * 256;
                v[u] = __ldcs(&ap[ii[u]]);
            }
#pragma unroll
            for (int u = 0; u < 8; u++) r[u] = g_rinv[ii[u] >> 9];
#pragma unroll
            for (int u = 0; u < 8; u++) {
                v[u].x *= r[u]; v[u].y *= r[u]; v[u].z *= r[u]; v[u].w *= r[u];
                __stcs(&ap[ii[u]], v[u]);
            }
        }
        return;
    }

    float* Asf = fsm;
    float* Bsf = fsm + 2 * 2560;

    const int gidb = bx >> 1;
    const int m0   = (gidb >> 3) * 128;
    const int n0   = (gidb & 7) * 128;
    const int lane = t & 31, warp = t >> 5;
    const int wm   = warp >> 1, wn = warp & 1;
    const int gid  = lane >> 2, tid4 = lane & 3;

    const int ar = t >> 1,  ac = (t & 1) * 8;
    const int br = t >> 4,  bc = (t & 15) * 8;

    const float* Aptr = Actx + (size_t)(m0 + ar) * 1024 + ac;
    const float* Wptr = Wo + (size_t)br * 1024 + n0 + bc;

    const uint32_t a_dst0 = smem_u32(&FAS(0, ar, ac));
    const uint32_t a_dst1 = smem_u32(&FAS(1, ar, ac));
    const uint32_t b_dst0 = smem_u32(&FBS(0, br, bc));
    const uint32_t b_dst1 = smem_u32(&FBS(1, br, bc));

    float acc[2][8][4];
#pragma unroll
    for (int i = 0; i < 2; i++)
#pragma unroll
        for (int j = 0; j < 8; j++)
#pragma unroll
            for (int c = 0; c < 4; c++) acc[i][j][c] = 0.f;

    CP_ASYNC16(a_dst0,      Aptr);
    CP_ASYNC16(a_dst0 + 16, Aptr + 4);
    CP_ASYNC16(b_dst0,      Wptr);
    CP_ASYNC16(b_dst0 + 16, Wptr + 4);
    CP_COMMIT();
    CP_ASYNC16(a_dst1,      Aptr + 16);
    CP_ASYNC16(a_dst1 + 16, Aptr + 20);
    CP_ASYNC16(b_dst1,      Wptr + 16384);
    CP_ASYNC16(b_dst1 + 16, Wptr + 16384 + 4);
    CP_COMMIT();

    for (int kt = 0; kt < 64; kt++) {
        const int cur = kt & 1;

        if (kt >= 63) CP_WAIT0(); else CP_WAIT1();
        __syncthreads();

#pragma unroll
        for (int s = 0; s < 2; s++) {
            unsigned af[2][4], bf[8][2];
#pragma unroll
            for (int i = 0; i < 2; i++) {
                const int r = wm * 32 + i * 16 + gid;
                const int kc = 8 * s + tid4;
                af[i][0] = f2tf32(FAS(cur, r, kc));
                af[i][1] = f2tf32(FAS(cur, r + 8, kc));
                af[i][2] = f2tf32(FAS(cur, r, kc + 4));
                af[i][3] = f2tf32(FAS(cur, r + 8, kc + 4));
            }
#pragma unroll
            for (int j = 0; j < 8; j++) {
                const int cn = wn * 64 + j * 8 + gid;
                bf[j][0] = f2tf32(FBS(cur, 8 * s + tid4, cn));
                bf[j][1] = f2tf32(FBS(cur, 8 * s + 4 + tid4, cn));
            }
#pragma unroll
            for (int i = 0; i < 2; i++)
#pragma unroll
                for (int j = 0; j < 8; j++) MMA_TF32(acc[i][j], af[i], bf[j]);
        }
        __syncthreads();

        if (kt + 2 < 64) {
            const int ko = (kt + 2) * 16;
            const uint32_t ad = cur ? a_dst1 : a_dst0;
            const uint32_t bd = cur ? b_dst1 : b_dst0;
            CP_ASYNC16(ad,      Aptr + ko);
            CP_ASYNC16(ad + 16, Aptr + ko + 4);
            CP_ASYNC16(bd,      Wptr + (size_t)ko * 1024);
            CP_ASYNC16(bd + 16, Wptr + (size_t)ko * 1024 + 4);
            CP_COMMIT();
        }
    }

#pragma unroll
    for (int i = 0; i < 2; i++) {
#pragma unroll
        for (int j = 0; j < 8; j++) {
            const int n = n0 + wn * 64 + j * 8 + tid4 * 2;
            const float b0 = bo[n], b1 = bo[n + 1];
#pragma unroll
            for (int half = 0; half < 2; half++) {
                const int m = m0 + wm * 32 + i * 16 + gid + half * 8;
                Cout[(size_t)m * 1024 + n]     = acc[i][j][half * 2 + 0] + b0;
                Cout[(size_t)m * 1024 + n + 1] = acc[i][j][half * 2 + 1] + b1;
            }
        }
    }
}

// ---------------------------------------------------------------------------
// MMA attention (frozen): 64 queries/CTA, 256 threads, register-prefetch
// double-buffered K/V, two barriers per tile, streaming P store.
// ---------------------------------------------------------------------------
#define KS(p, r, c) Ks[(p) * 4352 + (r) * 68 + (c)]
#define VS(p, r, c) Vs[(p) * 4352 + (r) * 68 + (c)]
#define PS(r, c)    Ps[(r) * 68 + (c)]
#define ATTN_SMEM_BYTES ((5 * 64 * 68 + 2 * 64 + 64) * 4)

__global__ __launch_bounds__(256, 2)
void attn_mma_kernel(const float* __restrict__ mask, float* __restrict__ attn)
{
    extern __shared__ char smem_raw[];
    unsigned* Ks = (unsigned*)smem_raw;
    unsigned* Vs = Ks + 2 * 4352;
    float*    Ps = (float*)(Vs + 2 * 4352);
    float*    Mt = Ps + 4352;
    float*    rowsum = Mt + 128;

    const int t    = threadIdx.x;
    const int bh   = blockIdx.y;
    const int b    = bh >> 4, h = bh & 15;
    const int q0   = blockIdx.x * 64;
    const int lane = t & 31, warp = t >> 5;
    const int gid  = lane >> 2, t4 = lane & 3;

    const int wmS = warp >> 2, wnS = warp & 3;
    const int wq  = warp >> 2, wd  = warp & 3;

    const float* __restrict__ Qbh = g_Qh + (size_t)bh * S_ * DEPTH_;
    const float* __restrict__ Kbh = g_Kh + (size_t)bh * S_ * DEPTH_;
    const float* __restrict__ Vbh = g_Vh + (size_t)bh * S_ * DEPTH_;

    unsigned qb[2][8][2];
#pragma unroll
    for (int j = 0; j < 2; j++) {
        const int qn = q0 + wnS * 16 + j * 8 + gid;
        const float* Qrow = Qbh + (size_t)qn * DEPTH_;
#pragma unroll
        for (int s = 0; s < 8; s++) {
            qb[j][s][0] = f2tf32(Qrow[8 * s + t4]);
            qb[j][s][1] = f2tf32(Qrow[8 * s + t4 + 4]);
        }
    }

    if (t < 64) rowsum[t] = 0.f;

    float Oa[2][2][4];
#pragma unroll
    for (int i = 0; i < 2; i++)
#pragma unroll
        for (int j = 0; j < 2; j++)
#pragma unroll
            for (int c = 0; c < 4; c++) Oa[i][j][c] = 0.f;
    float ps_part[2][2] = {{0.f, 0.f}, {0.f, 0.f}};

    float4 kreg[4], vreg[4];
    float  mreg = 0.f;
#pragma unroll
    for (int r = 0; r < 4; r++) {
        const int idx = t + 256 * r, key = idx >> 4, d4 = (idx & 15) * 4;
        kreg[r] = *(const float4*)&Kbh[(size_t)key * DEPTH_ + d4];
        vreg[r] = *(const float4*)&Vbh[(size_t)key * DEPTH_ + d4];
    }
    if (t < 64) mreg = mask[b * S_ + t] * NEG_;
#pragma unroll
    for (int r = 0; r < 4; r++) {
        const int idx = t + 256 * r, key = idx >> 4, d4 = (idx & 15) * 4;
        uint4 ku, vu;
        ku.x = f2tf32(kreg[r].x); ku.y = f2tf32(kreg[r].y);
        ku.z = f2tf32(kreg[r].z); ku.w = f2tf32(kreg[r].w);
        vu.x = f2tf32(vreg[r].x); vu.y = f2tf32(vreg[r].y);
        vu.z = f2tf32(vreg[r].z); vu.w = f2tf32(vreg[r].w);
        *(uint4*)&KS(0, key, d4) = ku;
        *(uint4*)&VS(0, key, d4) = vu;
    }
    if (t < 64) Mt[t] = mreg;
    __syncthreads();

    for (int kt = 0; kt < 32; kt++) {
        const int p = kt & 1;
        const int kb = kt * 64;

        if (kt < 31) {
            const int kb2 = kb + 64;
#pragma unroll
            for (int r = 0; r < 4; r++) {
                const int idx = t + 256 * r, key = idx >> 4, d4 = (idx & 15) * 4;
                kreg[r] = *(const float4*)&Kbh[(size_t)(kb2 + key) * DEPTH_ + d4];
                vreg[r] = *(const float4*)&Vbh[(size_t)(kb2 + key) * DEPTH_ + d4];
            }
            if (t < 64) mreg = mask[b * S_ + kb2 + t] * NEG_;
        }

        float sc[2][2][4];
#pragma unroll
        for (int i = 0; i < 2; i++)
#pragma unroll
            for (int j = 0; j < 2; j++)
#pragma unroll
                for (int c = 0; c < 4; c++) sc[i][j][c] = 0.f;

#pragma unroll
        for (int s = 0; s < 8; s++) {
            unsigned af[2][4];
#pragma unroll
            for (int i = 0; i < 2; i++) {
                const int r = wmS * 32 + i * 16 + gid;
                const int kc = 8 * s + t4;
                af[i][0] = KS(p, r, kc);     af[i][1] = KS(p, r + 8, kc);
                af[i][2] = KS(p, r, kc + 4); af[i][3] = KS(p, r + 8, kc + 4);
            }
#pragma unroll
            for (int i = 0; i < 2; i++)
#pragma unroll
                for (int j = 0; j < 2; j++) MMA_TF32(sc[i][j], af[i], qb[j][s]);
        }

#pragma unroll
        for (int i = 0; i < 2; i++) {
            const int kr = wmS * 32 + i * 16 + gid;
            const float m0 = Mt[p * 64 + kr], m1 = Mt[p * 64 + kr + 8];
#pragma unroll
            for (int j = 0; j < 2; j++) {
                const int qc = wnS * 16 + j * 8 + 2 * t4;
                const float p0 = __expf(sc[i][j][0] * SCALE_ + m0);
                const float p1 = __expf(sc[i][j][1] * SCALE_ + m0);
                const float p2 = __expf(sc[i][j][2] * SCALE_ + m1);
                const float p3 = __expf(sc[i][j][3] * SCALE_ + m1);
                PS(qc, kr)         = p0;
                PS(qc + 1, kr)     = p1;
                PS(qc, kr + 8)     = p2;
                PS(qc + 1, kr + 8) = p3;
                ps_part[j][0] += p0 + p2;
                ps_part[j][1] += p1 + p3;
            }
        }
        __syncthreads();   // syncA

        if (kt < 31) {
#pragma unroll
            for (int r = 0; r < 4; r++) {
                const int idx = t + 256 * r, key = idx >> 4, d4 = (idx & 15) * 4;
                uint4 ku, vu;
                ku.x = f2tf32(kreg[r].x); ku.y = f2tf32(kreg[r].y);
                ku.z = f2tf32(kreg[r].z); ku.w = f2tf32(kreg[r].w);
                vu.x = f2tf32(vreg[r].x); vu.y = f2tf32(vreg[r].y);
                vu.z = f2tf32(vreg[r].z); vu.w = f2tf32(vreg[r].w);
                *(uint4*)&KS(p ^ 1, key, d4) = ku;
                *(uint4*)&VS(p ^ 1, key, d4) = vu;
            }
            if (t < 64) Mt[(p ^ 1) * 64 + t] = mreg;
        }

#pragma unroll
        for (int r = 0; r < 4; r++) {
            const int idx = t + 256 * r, ql = idx >> 4, k4 = (idx & 15) * 4;
            const float4 pv = *(const float4*)&PS(ql, k4);
            __stcs((float4*)&attn[((size_t)(bh * S_ + q0 + ql)) * S_ + kb + k4], pv);
        }

#pragma unroll
        for (int s = 0; s < 8; s++) {
            unsigned af[2][4], bf[2][2];
#pragma unroll
            for (int i = 0; i < 2; i++) {
                const int qr = wq * 32 + i * 16 + gid;
                const int kc = 8 * s + t4;
                af[i][0] = f2tf32(PS(qr, kc));     af[i][1] = f2tf32(PS(qr + 8, kc));
                af[i][2] = f2tf32(PS(qr, kc + 4)); af[i][3] = f2tf32(PS(qr + 8, kc + 4));
            }
#pragma unroll
            for (int j = 0; j < 2; j++) {
                const int dn = wd * 16 + j * 8 + gid;
                bf[j][0] = VS(p, 8 * s + t4, dn);
                bf[j][1] = VS(p, 8 * s + 4 + t4, dn);
            }
#pragma unroll
            for (int i = 0; i < 2; i++)
#pragma unroll
                for (int j = 0; j < 2; j++) MMA_TF32(Oa[i][j], af[i], bf[j]);
        }
        __syncthreads();   // syncB
    }

#pragma unroll
    for (int j = 0; j < 2; j++)
#pragma unroll
        for (int c = 0; c < 2; c++) {
            float v = ps_part[j][c];
            v += __shfl_xor_sync(0xffffffffu, v, 4);
            v += __shfl_xor_sync(0xffffffffu, v, 8);
            v += __shfl_xor_sync(0xffffffffu, v, 16);
            ps_part[j][c] = v;
        }
    if (gid == 0) {
#pragma unroll
        for (int j = 0; j < 2; j++)
#pragma unroll
            for (int c = 0; c < 2; c++)
                atomicAdd(&rowsum[wnS * 16 + j * 8 + 2 * t4 + c], ps_part[j][c]);
    }
    __syncthreads();

    if (t < 64) g_rinv[(size_t)bh * S_ + q0 + t] = 1.0f / rowsum[t];

#pragma unroll
    for (int i = 0; i < 2; i++) {
        const int qr = wq * 32 + i * 16 + gid;
        const float r0 = 1.0f / rowsum[qr];
        const float r1 = 1.0f / rowsum[qr + 8];
#pragma unroll
        for (int j = 0; j < 2; j++) {
            const int dn = wd * 16 + j * 8 + 2 * t4;
            float* dst0 = &g_ctx[((size_t)(b * S_ + q0 + qr)) * D_ + h * DEPTH_ + dn];
            float* dst1 = &g_ctx[((size_t)(b * S_ + q0 + qr + 8)) * D_ + h * DEPTH_ + dn];
            dst0[0] = Oa[i][j][0] * r0; dst0[1] = Oa[i][j][1] * r0;
            dst1[0] = Oa[i][j][2] * r1; dst1[1] = Oa[i][j][3] * r1;
        }
    }
}

// ---------------------------------------------------------------------------
extern "C" void kernel_launch(void* const* d_in, const int* in_sizes, int n_in,
                              void* d_out, int out_size)
{
    const float* q    = (const float*)d_in[0];
    const float* k    = (const float*)d_in[1];
    const float* v    = (const float*)d_in[2];
    const float* mask = (const float*)d_in[3];
    const float* wq   = (const float*)d_in[4];
    const float* bq   = (const float*)d_in[5];
    const float* wk   = (const float*)d_in[6];
    const float* bk   = (const float*)d_in[7];
    const float* wv   = (const float*)d_in[8];
    const float* bv   = (const float*)d_in[9];
    const float* wo   = (const float*)d_in[10];
    const float* bo   = (const float*)d_in[11];

    float* out  = (float*)d_out;
    float* attn = out + (size_t)B_ * S_ * D_;

    float *pQh, *pKh, *pVh, *pCtx;
    cudaGetSymbolAddress((void**)&pQh,  g_Qh);
    cudaGetSymbolAddress((void**)&pKh,  g_Kh);
    cudaGetSymbolAddress((void**)&pVh,  g_Vh);
    cudaGetSymbolAddress((void**)&pCtx, g_ctx);

    static bool init_done = false;
    if (!init_done) {
        cudaFuncSetAttribute(attn_mma_kernel,
                             cudaFuncAttributeMaxDynamicSharedMemorySize,
                             ATTN_SMEM_BYTES);
        cudaFuncSetAttribute(gemm_qkv_kernel,
                             cudaFuncAttributeMaxDynamicSharedMemorySize,
                             QKV_SMEM_BYTES);
        cudaFuncSetAttribute(fused_out_norm_kernel,
                             cudaFuncAttributeMaxDynamicSharedMemorySize,
                             FUSED_SMEM_BYTES);
        init_done = true;
    }

    gemm_qkv_kernel<<<dim3(8, 16, 3), 512, QKV_SMEM_BYTES>>>(
        q, wq, bq, pQh,
        k, wk, bk, pKh,
        v, wv, bv, pVh);

    attn_mma_kernel<<<dim3(S_ / 64, B_ * H_), 256, ATTN_SMEM_BYTES>>>(mask, attn);

    fused_out_norm_kernel<<<FUSED_BLOCKS, 256, FUSED_SMEM_BYTES>>>(
        pCtx, wo, bo, out, attn);
}

// round 17
// speedup vs baseline: 1.0395x; 1.0395x over previous
#include <cuda_runtime.h>
#include <cstdint>

#define B_ 2
#define S_ 2048
#define D_ 1024
#define H_ 16
#define DEPTH_ 64
#define SCALE_ 0.125f
#define NEG_ (-1.0e9f)
#define L2E_ 1.44269504088896340736f
#define SCALE_L2E_ (SCALE_ * L2E_)
#define NEG_L2E_ (NEG_ * L2E_)

// Scratch (device globals — no allocations allowed)
__device__ float g_Qh[B_*H_*S_*DEPTH_];
__device__ float g_Kh[B_*H_*S_*DEPTH_];
__device__ float g_Vh[B_*H_*S_*DEPTH_];
__device__ float g_ctx[B_*S_*D_];
__device__ float g_rinv[B_*H_*S_];

__device__ __forceinline__ unsigned f2tf32(float f) {
    unsigned u; asm("cvt.rna.tf32.f32 %0, %1;" : "=r"(u) : "f"(f)); return u;
}

__device__ __forceinline__ float ex2f(float x) {
    float r; asm("ex2.approx.ftz.f32 %0, %1;" : "=f"(r) : "f"(x)); return r;
}

#define MMA_TF32(d, a, b)                                                     \
    asm volatile(                                                             \
        "mma.sync.aligned.m16n8k8.row.col.f32.tf32.tf32.f32 "                 \
        "{%0,%1,%2,%3},{%4,%5,%6,%7},{%8,%9},{%0,%1,%2,%3};"                  \
        : "+f"(d[0]), "+f"(d[1]), "+f"(d[2]), "+f"(d[3])                      \
        : "r"(a[0]), "r"(a[1]), "r"(a[2]), "r"(a[3]), "r"(b[0]), "r"(b[1]))

__device__ __forceinline__ uint32_t smem_u32(const void* p) {
    uint32_t a;
    asm("{ .reg .u64 t; cvta.to.shared.u64 t, %1; cvt.u32.u64 %0, t; }"
        : "=r"(a) : "l"(p));
    return a;
}

#define CP_ASYNC16(dst, src) \
    asm volatile("cp.async.cg.shared.global [%0], [%1], 16;" :: "r"(dst), "l"(src) : "memory")
#define CP_COMMIT() asm volatile("cp.async.commit_group;" ::: "memory")
#define CP_WAIT1()  asm volatile("cp.async.wait_group 1;" ::: "memory")
#define CP_WAIT0()  asm volatile("cp.async.wait_group 0;" ::: "memory")

// ---------------------------------------------------------------------------
// QKV tf32 GEMM: 256x128 CTA tile (512 threads), BK=16, 2-stage cp.async.
// (round-15 proven: 247 us for all three)
// ---------------------------------------------------------------------------
#define GASF(st, r, c) AsG[(st) * 5120 + (r) * 20 + (c)]
#define GBSF(st, r, c) BsG[(st) * 2112 + (r) * 132 + (c)]
#define QKV_SMEM_BYTES ((2 * 5120 + 2 * 2112) * 4)

__global__ __launch_bounds__(512, 1)
void gemm_qkv_kernel(const float* __restrict__ A0, const float* __restrict__ W0,
                     const float* __restrict__ bias0, float* __restrict__ C0,
                     const float* A1, const float* W1, const float* bias1, float* C1,
                     const float* A2, const float* W2, const float* bias2, float* C2)
{
    extern __shared__ float gsm[];
    float* AsG = gsm;
    float* BsG = gsm + 2 * 5120;

    const float* A = A0; const float* W = W0; const float* bias = bias0; float* C = C0;
    if (blockIdx.z == 1) { A = A1; W = W1; bias = bias1; C = C1; }
    else if (blockIdx.z == 2) { A = A2; W = W2; bias = bias2; C = C2; }

    const int t    = threadIdx.x;
    const int m0   = blockIdx.y * 256;
    const int n0   = blockIdx.x * 128;
    const int lane = t & 31, warp = t >> 5;
    const int wm   = warp >> 2, wn = warp & 3;
    const int gid  = lane >> 2, tid4 = lane & 3;

    const int ar = t >> 1,  ac = (t & 1) * 8;
    const int br = t >> 5,  bc = (t & 31) * 4;

    const float* Aptr = A + (size_t)(m0 + ar) * 1024 + ac;
    const float* Wptr = W + (size_t)br * 1024 + n0 + bc;

    uint32_t a_dst[2], b_dst[2];
#pragma unroll
    for (int s = 0; s < 2; s++) {
        a_dst[s] = smem_u32(&GASF(s, ar, ac));
        b_dst[s] = smem_u32(&GBSF(s, br, bc));
    }

    float acc[4][4][4];
#pragma unroll
    for (int i = 0; i < 4; i++)
#pragma unroll
        for (int j = 0; j < 4; j++)
#pragma unroll
            for (int c = 0; c < 4; c++) acc[i][j][c] = 0.f;

    CP_ASYNC16(a_dst[0],      Aptr);
    CP_ASYNC16(a_dst[0] + 16, Aptr + 4);
    CP_ASYNC16(b_dst[0],      Wptr);
    CP_COMMIT();
    CP_ASYNC16(a_dst[1],      Aptr + 16);
    CP_ASYNC16(a_dst[1] + 16, Aptr + 20);
    CP_ASYNC16(b_dst[1],      Wptr + 16384);
    CP_COMMIT();

    for (int kt = 0; kt < 64; kt++) {
        const int cur = kt & 1;

        if (kt >= 63) CP_WAIT0(); else CP_WAIT1();
        __syncthreads();

#pragma unroll
        for (int s = 0; s < 2; s++) {
            unsigned af[4][4], bf[4][2];
#pragma unroll
            for (int i = 0; i < 4; i++) {
                const int r = wm * 64 + i * 16 + gid;
                const int kc = 8 * s + tid4;
                af[i][0] = f2tf32(GASF(cur, r, kc));
                af[i][1] = f2tf32(GASF(cur, r + 8, kc));
                af[i][2] = f2tf32(GASF(cur, r, kc + 4));
                af[i][3] = f2tf32(GASF(cur, r + 8, kc + 4));
            }
#pragma unroll
            for (int j = 0; j < 4; j++) {
                const int cn = wn * 32 + j * 8 + gid;
                bf[j][0] = f2tf32(GBSF(cur, 8 * s + tid4, cn));
                bf[j][1] = f2tf32(GBSF(cur, 8 * s + 4 + tid4, cn));
            }
#pragma unroll
            for (int i = 0; i < 4; i++)
#pragma unroll
                for (int j = 0; j < 4; j++) MMA_TF32(acc[i][j], af[i], bf[j]);
        }
        __syncthreads();

        if (kt + 2 < 64) {
            const int ko = (kt + 2) * 16;
            CP_ASYNC16(a_dst[cur],      Aptr + ko);
            CP_ASYNC16(a_dst[cur] + 16, Aptr + ko + 4);
            CP_ASYNC16(b_dst[cur],      Wptr + (size_t)ko * 1024);
            CP_COMMIT();
        }
    }

#pragma unroll
    for (int i = 0; i < 4; i++) {
#pragma unroll
        for (int j = 0; j < 4; j++) {
            const int n = n0 + wn * 32 + j * 8 + tid4 * 2;
            const float b0 = bias[n], b1 = bias[n + 1];
#pragma unroll
            for (int half = 0; half < 2; half++) {
                const int m = m0 + wm * 64 + i * 16 + gid + half * 8;
                const float v0 = acc[i][j][half * 2 + 0] + b0;
                const float v1 = acc[i][j][half * 2 + 1] + b1;
                const int bb = m >> 11, s = m & 2047;
                const int h = n >> 6, dd = n & 63;
                float* dst = &C[(((size_t)(bb * H_ + h) << 11) + s) * DEPTH_ + dd];
                dst[0] = v0; dst[1] = v1;
            }
        }
    }
}

// ---------------------------------------------------------------------------
// FUSED tail kernel: out-projection GEMM (interleaved 256 blocks) + attn
// normalization (8192 streaming blocks, MLP-8, streaming hints). (round-15)
// ---------------------------------------------------------------------------
#define FAS(st, r, c) Asf[(st) * 2560 + (r) * 20 + (c)]
#define FBS(st, r, c) Bsf[(st) * 2112 + (r) * 132 + (c)]
#define FUSED_SMEM_BYTES ((2 * 2560 + 2 * 2112) * 4)
#define NORM_F4_PER_BLOCK 4096
#define FUSED_BLOCKS (512 + 8192 - 256)

__global__ __launch_bounds__(256, 2)
void fused_out_norm_kernel(const float* __restrict__ Actx,
                           const float* __restrict__ Wo,
                           const float* __restrict__ bo,
                           float* __restrict__ Cout,
                           float* __restrict__ attn)
{
    extern __shared__ float fsm[];
    const int bx = blockIdx.x;
    const int t  = threadIdx.x;

    const bool is_gemm = (bx < 512) && ((bx & 1) == 0);

    if (!is_gemm) {
        const int nidx = (bx < 512) ? (bx >> 1) : (256 + (bx - 512));
        float4* ap = (float4*)attn;
        const size_t base = (size_t)nidx * NORM_F4_PER_BLOCK + t;
#pragma unroll
        for (int g = 0; g < 2; g++) {
            float4 v[8]; float r[8]; size_t ii[8];
#pragma unroll
            for (int u = 0; u < 8; u++) {
                ii[u] = base + (g * 8 + u) * 256;
                v[u] = __ldcs(&ap[ii[u]]);
            }
#pragma unroll
            for (int u = 0; u < 8; u++) r[u] = g_rinv[ii[u] >> 9];
#pragma unroll
            for (int u = 0; u < 8; u++) {
                v[u].x *= r[u]; v[u].y *= r[u]; v[u].z *= r[u]; v[u].w *= r[u];
                __stcs(&ap[ii[u]], v[u]);
            }
        }
        return;
    }

    float* Asf = fsm;
    float* Bsf = fsm + 2 * 2560;

    const int gidb = bx >> 1;
    const int m0   = (gidb >> 3) * 128;
    const int n0   = (gidb & 7) * 128;
    const int lane = t & 31, warp = t >> 5;
    const int wm   = warp >> 1, wn = warp & 1;
    const int gid  = lane >> 2, tid4 = lane & 3;

    const int ar = t >> 1,  ac = (t & 1) * 8;
    const int br = t >> 4,  bc = (t & 15) * 8;

    const float* Aptr = Actx + (size_t)(m0 + ar) * 1024 + ac;
    const float* Wptr = Wo + (size_t)br * 1024 + n0 + bc;

    const uint32_t a_dst0 = smem_u32(&FAS(0, ar, ac));
    const uint32_t a_dst1 = smem_u32(&FAS(1, ar, ac));
    const uint32_t b_dst0 = smem_u32(&FBS(0, br, bc));
    const uint32_t b_dst1 = smem_u32(&FBS(1, br, bc));

    float acc[2][8][4];
#pragma unroll
    for (int i = 0; i < 2; i++)
#pragma unroll
        for (int j = 0; j < 8; j++)
#pragma unroll
            for (int c = 0; c < 4; c++) acc[i][j][c] = 0.f;

    CP_ASYNC16(a_dst0,      Aptr);
    CP_ASYNC16(a_dst0 + 16, Aptr + 4);
    CP_ASYNC16(b_dst0,      Wptr);
    CP_ASYNC16(b_dst0 + 16, Wptr + 4);
    CP_COMMIT();
    CP_ASYNC16(a_dst1,      Aptr + 16);
    CP_ASYNC16(a_dst1 + 16, Aptr + 20);
    CP_ASYNC16(b_dst1,      Wptr + 16384);
    CP_ASYNC16(b_dst1 + 16, Wptr + 16384 + 4);
    CP_COMMIT();

    for (int kt = 0; kt < 64; kt++) {
        const int cur = kt & 1;

        if (kt >= 63) CP_WAIT0(); else CP_WAIT1();
        __syncthreads();

#pragma unroll
        for (int s = 0; s < 2; s++) {
            unsigned af[2][4], bf[8][2];
#pragma unroll
            for (int i = 0; i < 2; i++) {
                const int r = wm * 32 + i * 16 + gid;
                const int kc = 8 * s + tid4;
                af[i][0] = f2tf32(FAS(cur, r, kc));
                af[i][1] = f2tf32(FAS(cur, r + 8, kc));
                af[i][2] = f2tf32(FAS(cur, r, kc + 4));
                af[i][3] = f2tf32(FAS(cur, r + 8, kc + 4));
            }
#pragma unroll
            for (int j = 0; j < 8; j++) {
                const int cn = wn * 64 + j * 8 + gid;
                bf[j][0] = f2tf32(FBS(cur, 8 * s + tid4, cn));
                bf[j][1] = f2tf32(FBS(cur, 8 * s + 4 + tid4, cn));
            }
#pragma unroll
            for (int i = 0; i < 2; i++)
#pragma unroll
                for (int j = 0; j < 8; j++) MMA_TF32(acc[i][j], af[i], bf[j]);
        }
        __syncthreads();

        if (kt + 2 < 64) {
            const int ko = (kt + 2) * 16;
            const uint32_t ad = cur ? a_dst1 : a_dst0;
            const uint32_t bd = cur ? b_dst1 : b_dst0;
            CP_ASYNC16(ad,      Aptr + ko);
            CP_ASYNC16(ad + 16, Aptr + ko + 4);
            CP_ASYNC16(bd,      Wptr + (size_t)ko * 1024);
            CP_ASYNC16(bd + 16, Wptr + (size_t)ko * 1024 + 4);
            CP_COMMIT();
        }
    }

#pragma unroll
    for (int i = 0; i < 2; i++) {
#pragma unroll
        for (int j = 0; j < 8; j++) {
            const int n = n0 + wn * 64 + j * 8 + tid4 * 2;
            const float b0 = bo[n], b1 = bo[n + 1];
#pragma unroll
            for (int half = 0; half < 2; half++) {
                const int m = m0 + wm * 32 + i * 16 + gid + half * 8;
                Cout[(size_t)m * 1024 + n]     = acc[i][j][half * 2 + 0] + b0;
                Cout[(size_t)m * 1024 + n + 1] = acc[i][j][half * 2 + 1] + b1;
            }
        }
    }
}

// ---------------------------------------------------------------------------
// MMA attention (frozen shape): 64 queries/CTA, 256 threads, register-prefetch
// double-buffered K/V, two barriers per tile, streaming P store.
// exp via folded log2e: one FFMA + EX2 per element (shorter critical path).
// ---------------------------------------------------------------------------
#define KS(p, r, c) Ks[(p) * 4352 + (r) * 68 + (c)]
#define VS(p, r, c) Vs[(p) * 4352 + (r) * 68 + (c)]
#define PS(r, c)    Ps[(r) * 68 + (c)]
#define ATTN_SMEM_BYTES ((5 * 64 * 68 + 2 * 64 + 64) * 4)

__global__ __launch_bounds__(256, 2)
void attn_mma_kernel(const float* __restrict__ mask, float* __restrict__ attn)
{
    extern __shared__ char smem_raw[];
    unsigned* Ks = (unsigned*)smem_raw;
    unsigned* Vs = Ks + 2 * 4352;
    float*    Ps = (float*)(Vs + 2 * 4352);
    float*    Mt = Ps + 4352;
    float*    rowsum = Mt + 128;

    const int t    = threadIdx.x;
    const int bh   = blockIdx.y;
    const int b    = bh >> 4, h = bh & 15;
    const int q0   = blockIdx.x * 64;
    const int lane = t & 31, warp = t >> 5;
    const int gid  = lane >> 2, t4 = lane & 3;

    const int wmS = warp >> 2, wnS = warp & 3;
    const int wq  = warp >> 2, wd  = warp & 3;

    const float* __restrict__ Qbh = g_Qh + (size_t)bh * S_ * DEPTH_;
    const float* __restrict__ Kbh = g_Kh + (size_t)bh * S_ * DEPTH_;
    const float* __restrict__ Vbh = g_Vh + (size_t)bh * S_ * DEPTH_;

    unsigned qb[2][8][2];
#pragma unroll
    for (int j = 0; j < 2; j++) {
        const int qn = q0 + wnS * 16 + j * 8 + gid;
        const float* Qrow = Qbh + (size_t)qn * DEPTH_;
#pragma unroll
        for (int s = 0; s < 8; s++) {
            qb[j][s][0] = f2tf32(Qrow[8 * s + t4]);
            qb[j][s][1] = f2tf32(Qrow[8 * s + t4 + 4]);
        }
    }

    if (t < 64) rowsum[t] = 0.f;

    float Oa[2][2][4];
#pragma unroll
    for (int i = 0; i < 2; i++)
#pragma unroll
        for (int j = 0; j < 2; j++)
#pragma unroll
            for (int c = 0; c < 4; c++) Oa[i][j][c] = 0.f;
    float ps_part[2][2] = {{0.f, 0.f}, {0.f, 0.f}};

    float4 kreg[4], vreg[4];
    float  mreg = 0.f;
#pragma unroll
    for (int r = 0; r < 4; r++) {
        const int idx = t + 256 * r, key = idx >> 4, d4 = (idx & 15) * 4;
        kreg[r] = *(const float4*)&Kbh[(size_t)key * DEPTH_ + d4];
        vreg[r] = *(const float4*)&Vbh[(size_t)key * DEPTH_ + d4];
    }
    if (t < 64) mreg = mask[b * S_ + t] * NEG_L2E_;
#pragma unroll
    for (int r = 0; r < 4; r++) {
        const int idx = t + 256 * r, key = idx >> 4, d4 = (idx & 15) * 4;
        uint4 ku, vu;
        ku.x = f2tf32(kreg[r].x); ku.y = f2tf32(kreg[r].y);
        ku.z = f2tf32(kreg[r].z); ku.w = f2tf32(kreg[r].w);
        vu.x = f2tf32(vreg[r].x); vu.y = f2tf32(vreg[r].y);
        vu.z = f2tf32(vreg[r].z); vu.w = f2tf32(vreg[r].w);
        *(uint4*)&KS(0, key, d4) = ku;
        *(uint4*)&VS(0, key, d4) = vu;
    }
    if (t < 64) Mt[t] = mreg;
    __syncthreads();

    for (int kt = 0; kt < 32; kt++) {
        const int p = kt & 1;
        const int kb = kt * 64;

        if (kt < 31) {
            const int kb2 = kb + 64;
#pragma unroll
            for (int r = 0; r < 4; r++) {
                const int idx = t + 256 * r, key = idx >> 4, d4 = (idx & 15) * 4;
                kreg[r] = *(const float4*)&Kbh[(size_t)(kb2 + key) * DEPTH_ + d4];
                vreg[r] = *(const float4*)&Vbh[(size_t)(kb2 + key) * DEPTH_ + d4];
            }
            if (t < 64) mreg = mask[b * S_ + kb2 + t] * NEG_L2E_;
        }

        float sc[2][2][4];
#pragma unroll
        for (int i = 0; i < 2; i++)
#pragma unroll
            for (int j = 0; j < 2; j++)
#pragma unroll
                for (int c = 0; c < 4; c++) sc[i][j][c] = 0.f;

#pragma unroll
        for (int s = 0; s < 8; s++) {
            unsigned af[2][4];
#pragma unroll
            for (int i = 0; i < 2; i++) {
                const int r = wmS * 32 + i * 16 + gid;
                const int kc = 8 * s + t4;
                af[i][0] = KS(p, r, kc);     af[i][1] = KS(p, r + 8, kc);
                af[i][2] = KS(p, r, kc + 4); af[i][3] = KS(p, r + 8, kc + 4);
            }
#pragma unroll
            for (int i = 0; i < 2; i++)
#pragma unroll
                for (int j = 0; j < 2; j++) MMA_TF32(sc[i][j], af[i], qb[j][s]);
        }

        // exp: p = ex2(sc * (SCALE*log2e) + mask*NEG*log2e)  — FFMA + EX2
#pragma unroll
        for (int i = 0; i < 2; i++) {
            const int kr = wmS * 32 + i * 16 + gid;
            const float m0 = Mt[p * 64 + kr], m1 = Mt[p * 64 + kr + 8];
#pragma unroll
            for (int j = 0; j < 2; j++) {
                const int qc = wnS * 16 + j * 8 + 2 * t4;
                const float p0 = ex2f(fmaf(sc[i][j][0], SCALE_L2E_, m0));
                const float p1 = ex2f(fmaf(sc[i][j][1], SCALE_L2E_, m0));
                const float p2 = ex2f(fmaf(sc[i][j][2], SCALE_L2E_, m1));
                const float p3 = ex2f(fmaf(sc[i][j][3], SCALE_L2E_, m1));
                PS(qc, kr)         = p0;
                PS(qc + 1, kr)     = p1;
                PS(qc, kr + 8)     = p2;
                PS(qc + 1, kr + 8) = p3;
                ps_part[j][0] += p0 + p2;
                ps_part[j][1] += p1 + p3;
            }
        }
        __syncthreads();   // syncA

        if (kt < 31) {
#pragma unroll
            for (int r = 0; r < 4; r++) {
                const int idx = t + 256 * r, key = idx >> 4, d4 = (idx & 15) * 4;
                uint4 ku, vu;
                ku.x = f2tf32(kreg[r].x); ku.y = f2tf32(kreg[r].y);
                ku.z = f2tf32(kreg[r].z); ku.w = f2tf32(kreg[r].w);
                vu.x = f2tf32(vreg[r].x); vu.y = f2tf32(vreg[r].y);
                vu.z = f2tf32(vreg[r].z); vu.w = f2tf32(vreg[r].w);
                *(uint4*)&KS(p ^ 1, key, d4) = ku;
                *(uint4*)&VS(p ^ 1, key, d4) = vu;
            }
            if (t < 64) Mt[(p ^ 1) * 64 + t] = mreg;
        }

#pragma unroll
        for (int r = 0; r < 4; r++) {
            const int idx = t + 256 * r, ql = idx >> 4, k4 = (idx & 15) * 4;
            const float4 pv = *(const float4*)&PS(ql, k4);
            __stcs((float4*)&attn[((size_t)(bh * S_ + q0 + ql)) * S_ + kb + k4], pv);
        }

#pragma unroll
        for (int s = 0; s < 8; s++) {
            unsigned af[2][4], bf[2][2];
#pragma unroll
            for (int i = 0; i < 2; i++) {
                const int qr = wq * 32 + i * 16 + gid;
                const int kc = 8 * s + t4;
                af[i][0] = f2tf32(PS(qr, kc));     af[i][1] = f2tf32(PS(qr + 8, kc));
                af[i][2] = f2tf32(PS(qr, kc + 4)); af[i][3] = f2tf32(PS(qr + 8, kc + 4));
            }
#pragma unroll
            for (int j = 0; j < 2; j++) {
                const int dn = wd * 16 + j * 8 + gid;
                bf[j][0] = VS(p, 8 * s + t4, dn);
                bf[j][1] = VS(p, 8 * s + 4 + t4, dn);
            }
#pragma unroll
            for (int i = 0; i < 2; i++)
#pragma unroll
                for (int j = 0; j < 2; j++) MMA_TF32(Oa[i][j], af[i], bf[j]);
        }
        __syncthreads();   // syncB
    }

#pragma unroll
    for (int j = 0; j < 2; j++)
#pragma unroll
        for (int c = 0; c < 2; c++) {
            float v = ps_part[j][c];
            v += __shfl_xor_sync(0xffffffffu, v, 4);
            v += __shfl_xor_sync(0xffffffffu, v, 8);
            v += __shfl_xor_sync(0xffffffffu, v, 16);
            ps_part[j][c] = v;
        }
    if (gid == 0) {
#pragma unroll
        for (int j = 0; j < 2; j++)
#pragma unroll
            for (int c = 0; c < 2; c++)
                atomicAdd(&rowsum[wnS * 16 + j * 8 + 2 * t4 + c], ps_part[j][c]);
    }
    __syncthreads();

    if (t < 64) g_rinv[(size_t)bh * S_ + q0 + t] = 1.0f / rowsum[t];

#pragma unroll
    for (int i = 0; i < 2; i++) {
        const int qr = wq * 32 + i * 16 + gid;
        const float r0 = 1.0f / rowsum[qr];
        const float r1 = 1.0f / rowsum[qr + 8];
#pragma unroll
        for (int j = 0; j < 2; j++) {
            const int dn = wd * 16 + j * 8 + 2 * t4;
            float* dst0 = &g_ctx[((size_t)(b * S_ + q0 + qr)) * D_ + h * DEPTH_ + dn];
            float* dst1 = &g_ctx[((size_t)(b * S_ + q0 + qr + 8)) * D_ + h * DEPTH_ + dn];
            dst0[0] = Oa[i][j][0] * r0; dst0[1] = Oa[i][j][1] * r0;
            dst1[0] = Oa[i][j][2] * r1; dst1[1] = Oa[i][j][3] * r1;
        }
    }
}

// ---------------------------------------------------------------------------
extern "C" void kernel_launch(void* const* d_in, const int* in_sizes, int n_in,
                              void* d_out, int out_size)
{
    const float* q    = (const float*)d_in[0];
    const float* k    = (const float*)d_in[1];
    const float* v    = (const float*)d_in[2];
    const float* mask = (const float*)d_in[3];
    const float* wq   = (const float*)d_in[4];
    const float* bq   = (const float*)d_in[5];
    const float* wk   = (const float*)d_in[6];
    const float* bk   = (const float*)d_in[7];
    const float* wv   = (const float*)d_in[8];
    const float* bv   = (const float*)d_in[9];
    const float* wo   = (const float*)d_in[10];
    const float* bo   = (const float*)d_in[11];

    float* out  = (float*)d_out;
    float* attn = out + (size_t)B_ * S_ * D_;

    float *pQh, *pKh, *pVh, *pCtx;
    cudaGetSymbolAddress((void**)&pQh,  g_Qh);
    cudaGetSymbolAddress((void**)&pKh,  g_Kh);
    cudaGetSymbolAddress((void**)&pVh,  g_Vh);
    cudaGetSymbolAddress((void**)&pCtx, g_ctx);

    static bool init_done = false;
    if (!init_done) {
        cudaFuncSetAttribute(attn_mma_kernel,
                             cudaFuncAttributeMaxDynamicSharedMemorySize,
                             ATTN_SMEM_BYTES);
        cudaFuncSetAttribute(gemm_qkv_kernel,
                             cudaFuncAttributeMaxDynamicSharedMemorySize,
                             QKV_SMEM_BYTES);
        cudaFuncSetAttribute(fused_out_norm_kernel,
                             cudaFuncAttributeMaxDynamicSharedMemorySize,
                             FUSED_SMEM_BYTES);
        init_done = true;
    }

    gemm_qkv_kernel<<<dim3(8, 16, 3), 512, QKV_SMEM_BYTES>>>(
        q, wq, bq, pQh,
        k, wk, bk, pKh,
        v, wv, bv, pVh);

    attn_mma_kernel<<<dim3(S_ / 64, B_ * H_), 256, ATTN_SMEM_BYTES>>>(mask, attn);

    fused_out_norm_kernel<<<FUSED_BLOCKS, 256, FUSED_SMEM_BYTES>>>(
        pCtx, wo, bo, out, attn);
}